// round 1
// baseline (speedup 1.0000x reference)
#include <cuda_runtime.h>

#define B_ 4
#define S_ 2048
#define DM_ 1024
#define H_ 16
#define DK_ 64
#define M_ (B_ * S_)   // 8192

// Scratch (device globals; allocation-free per harness rules)
__device__ float g_Q[B_ * H_ * S_ * DK_];
__device__ float g_K[B_ * H_ * S_ * DK_];
__device__ float g_V[B_ * H_ * S_ * DK_];
__device__ float g_MH[B_ * S_ * DM_];

// ---------------------------------------------------------------------------
// GEMM: C[m,n] = sum_k A[m,k] * W[n,k]   (A: [M,1024], W: [1024,1024])
// headSplit=1 -> C stored as [B,H,S,DK] with n = h*64+dk ; else [M,1024]
// 128x128 block tile, BK=16 double buffered, 256 threads, 8x8 micro tile
// ---------------------------------------------------------------------------
__global__ __launch_bounds__(256) void gemm_nt_kernel(
    const float* __restrict__ A, const float* __restrict__ W,
    float* __restrict__ C, int headSplit)
{
    __shared__ float As[2][16][128];
    __shared__ float Bs[2][16][128];

    const int tid = threadIdx.x;
    const int tx = tid & 15;
    const int ty = tid >> 4;
    const int m0 = blockIdx.y * 128;
    const int n0 = blockIdx.x * 128;

    float acc[8][8];
#pragma unroll
    for (int i = 0; i < 8; i++)
#pragma unroll
        for (int j = 0; j < 8; j++) acc[i][j] = 0.f;

    auto ldTile = [&](int buf, int kt) {
#pragma unroll
        for (int i = 0; i < 2; i++) {
            int f   = tid + i * 256;     // 512 float4 per operand tile
            int row = f >> 2;            // 4 float4 per row (BK=16)
            int c   = (f & 3) << 2;
            float4 va = *reinterpret_cast<const float4*>(A + (m0 + row) * 1024 + kt + c);
            As[buf][c + 0][row] = va.x;
            As[buf][c + 1][row] = va.y;
            As[buf][c + 2][row] = va.z;
            As[buf][c + 3][row] = va.w;
            float4 vb = *reinterpret_cast<const float4*>(W + (n0 + row) * 1024 + kt + c);
            Bs[buf][c + 0][row] = vb.x;
            Bs[buf][c + 1][row] = vb.y;
            Bs[buf][c + 2][row] = vb.z;
            Bs[buf][c + 3][row] = vb.w;
        }
    };

    ldTile(0, 0);
    __syncthreads();

#pragma unroll 1
    for (int t = 0; t < 64; t++) {
        int buf = t & 1;
        if (t < 63) ldTile(buf ^ 1, (t + 1) * 16);

#pragma unroll
        for (int kk = 0; kk < 16; kk++) {
            float4 a0 = *reinterpret_cast<const float4*>(&As[buf][kk][ty * 4]);
            float4 a1 = *reinterpret_cast<const float4*>(&As[buf][kk][ty * 4 + 64]);
            float4 b0 = *reinterpret_cast<const float4*>(&Bs[buf][kk][tx * 4]);
            float4 b1 = *reinterpret_cast<const float4*>(&Bs[buf][kk][tx * 4 + 64]);
            float ra[8] = {a0.x, a0.y, a0.z, a0.w, a1.x, a1.y, a1.z, a1.w};
            float rb[8] = {b0.x, b0.y, b0.z, b0.w, b1.x, b1.y, b1.z, b1.w};
#pragma unroll
            for (int i = 0; i < 8; i++)
#pragma unroll
                for (int j = 0; j < 8; j++)
                    acc[i][j] = fmaf(ra[i], rb[j], acc[i][j]);
        }
        __syncthreads();
    }

    // epilogue
#pragma unroll
    for (int i = 0; i < 8; i++) {
        int m = m0 + ty * 4 + ((i >> 2) << 6) + (i & 3);
        int b = m >> 11;       // / 2048
        int s = m & 2047;
#pragma unroll
        for (int jh = 0; jh < 2; jh++) {
            int n = n0 + tx * 4 + jh * 64;
            float4 o = make_float4(acc[i][jh * 4 + 0], acc[i][jh * 4 + 1],
                                   acc[i][jh * 4 + 2], acc[i][jh * 4 + 3]);
            if (headSplit) {
                int h = n >> 6, dk = n & 63;
                *reinterpret_cast<float4*>(&C[(((b * H_ + h) * S_) + s) * DK_ + dk]) = o;
            } else {
                *reinterpret_cast<float4*>(&C[m * 1024 + n]) = o;
            }
        }
    }
}

// ---------------------------------------------------------------------------
// Flash attention, fp32. Grid: (S/64, H, B). 256 threads = 16x16, 4x4 tiles.
// Qs: d-major [d][row] (scaled by 1/8). KPs: K as [d][col], reused as P [row][col].
// Vs: natural [j][dk].
// ---------------------------------------------------------------------------
__global__ __launch_bounds__(256) void attn_kernel(
    const float* __restrict__ Qp, const float* __restrict__ Kp,
    const float* __restrict__ Vp, const int* __restrict__ mask,
    float* __restrict__ MH)
{
    __shared__ float Qs[64 * 64];
    __shared__ float KPs[64 * 64];
    __shared__ float Vs[64 * 64];

    const int tid = threadIdx.x;
    const int tx = tid & 15;
    const int ty = tid >> 4;
    const int qb = blockIdx.x;
    const int h  = blockIdx.y;
    const int b  = blockIdx.z;

    const float* Qbh = Qp + ((b * H_ + h) * S_) * DK_;
    const float* Kbh = Kp + ((b * H_ + h) * S_) * DK_;
    const float* Vbh = Vp + ((b * H_ + h) * S_) * DK_;
    const int* mrow = mask + b * S_;
    const int q0 = qb * 64;

    // load Q tile transposed (d-major), pre-scaled by 1/sqrt(dk)=0.125
#pragma unroll
    for (int i = 0; i < 4; i++) {
        int f   = tid + i * 256;   // 1024 float4
        int row = f >> 4;          // 16 float4 per row
        int c   = (f & 15) << 2;
        float4 v = *reinterpret_cast<const float4*>(Qbh + (q0 + row) * 64 + c);
        Qs[(c + 0) * 64 + row] = v.x * 0.125f;
        Qs[(c + 1) * 64 + row] = v.y * 0.125f;
        Qs[(c + 2) * 64 + row] = v.z * 0.125f;
        Qs[(c + 3) * 64 + row] = v.w * 0.125f;
    }

    float accO[4][4];
    float mr[4], lr[4];
#pragma unroll
    for (int i = 0; i < 4; i++) {
        mr[i] = -1e30f;
        lr[i] = 0.f;
#pragma unroll
        for (int j = 0; j < 4; j++) accO[i][j] = 0.f;
    }

    for (int kb = 0; kb < 32; kb++) {
        __syncthreads();   // prev iter's P/V reads done (and Q stores visible on kb==0)

        // load K (transposed -> [d][col]) and V (natural -> [j][dk])
#pragma unroll
        for (int i = 0; i < 4; i++) {
            int f   = tid + i * 256;
            int row = f >> 4;
            int c   = (f & 15) << 2;
            float4 kv = *reinterpret_cast<const float4*>(Kbh + (kb * 64 + row) * 64 + c);
            KPs[(c + 0) * 64 + row] = kv.x;
            KPs[(c + 1) * 64 + row] = kv.y;
            KPs[(c + 2) * 64 + row] = kv.z;
            KPs[(c + 3) * 64 + row] = kv.w;
            float4 vv = *reinterpret_cast<const float4*>(Vbh + (kb * 64 + row) * 64 + c);
            *reinterpret_cast<float4*>(&Vs[row * 64 + c]) = vv;
        }
        __syncthreads();

        // S = Q @ K^T (scaled already)
        float s[4][4];
#pragma unroll
        for (int i = 0; i < 4; i++)
#pragma unroll
            for (int j = 0; j < 4; j++) s[i][j] = 0.f;

#pragma unroll 8
        for (int d = 0; d < 64; d++) {
            float4 a = *reinterpret_cast<const float4*>(&Qs[d * 64 + ty * 4]);
            float4 bb = *reinterpret_cast<const float4*>(&KPs[d * 64 + tx * 4]);
            float ra[4] = {a.x, a.y, a.z, a.w};
            float rb[4] = {bb.x, bb.y, bb.z, bb.w};
#pragma unroll
            for (int ii = 0; ii < 4; ii++)
#pragma unroll
                for (int jj = 0; jj < 4; jj++)
                    s[ii][jj] = fmaf(ra[ii], rb[jj], s[ii][jj]);
        }

        // mask (mask==0 -> -1e9)
#pragma unroll
        for (int jj = 0; jj < 4; jj++) {
            int mv = mrow[kb * 64 + tx * 4 + jj];
            if (mv == 0) {
#pragma unroll
                for (int ii = 0; ii < 4; ii++) s[ii][jj] = -1e9f;
            }
        }

        // online softmax bookkeeping
        float alpha[4];
#pragma unroll
        for (int ii = 0; ii < 4; ii++) {
            float rmax = fmaxf(fmaxf(s[ii][0], s[ii][1]), fmaxf(s[ii][2], s[ii][3]));
#pragma unroll
            for (int o = 8; o >= 1; o >>= 1)
                rmax = fmaxf(rmax, __shfl_xor_sync(0xffffffffu, rmax, o));
            float mn = fmaxf(mr[ii], rmax);
            alpha[ii] = __expf(mr[ii] - mn);
            mr[ii] = mn;
            float rsum = 0.f;
#pragma unroll
            for (int jj = 0; jj < 4; jj++) {
                s[ii][jj] = __expf(s[ii][jj] - mn);
                rsum += s[ii][jj];
            }
#pragma unroll
            for (int o = 8; o >= 1; o >>= 1)
                rsum += __shfl_xor_sync(0xffffffffu, rsum, o);
            lr[ii] = lr[ii] * alpha[ii] + rsum;
#pragma unroll
            for (int jj = 0; jj < 4; jj++) accO[ii][jj] *= alpha[ii];
        }

        __syncthreads();   // all threads done reading KPs (K)
        // write P (natural layout [row][col]) into KPs
#pragma unroll
        for (int ii = 0; ii < 4; ii++) {
            float4 p = make_float4(s[ii][0], s[ii][1], s[ii][2], s[ii][3]);
            *reinterpret_cast<float4*>(&KPs[(ty * 4 + ii) * 64 + tx * 4]) = p;
        }
        __syncthreads();

        // O += P @ V
#pragma unroll 8
        for (int j = 0; j < 64; j++) {
            float4 vv = *reinterpret_cast<const float4*>(&Vs[j * 64 + tx * 4]);
            float rv[4] = {vv.x, vv.y, vv.z, vv.w};
            float rp[4];
#pragma unroll
            for (int ii = 0; ii < 4; ii++) rp[ii] = KPs[(ty * 4 + ii) * 64 + j];
#pragma unroll
            for (int ii = 0; ii < 4; ii++)
#pragma unroll
                for (int jj = 0; jj < 4; jj++)
                    accO[ii][jj] = fmaf(rp[ii], rv[jj], accO[ii][jj]);
        }
    }

    // epilogue: normalize and write merged-head layout [B,S,D]
#pragma unroll
    for (int ii = 0; ii < 4; ii++) {
        float inv = 1.f / lr[ii];
        int srow = q0 + ty * 4 + ii;
        float4 o = make_float4(accO[ii][0] * inv, accO[ii][1] * inv,
                               accO[ii][2] * inv, accO[ii][3] * inv);
        *reinterpret_cast<float4*>(&MH[(b * S_ + srow) * DM_ + h * 64 + tx * 4]) = o;
    }
}

// ---------------------------------------------------------------------------
extern "C" void kernel_launch(void* const* d_in, const int* in_sizes, int n_in,
                              void* d_out, int out_size)
{
    const float* q    = (const float*)d_in[0];
    const float* k    = (const float*)d_in[1];
    const float* v    = (const float*)d_in[2];
    const int*   mask = (const int*)d_in[3];
    const float* Wq   = (const float*)d_in[4];
    const float* Wk   = (const float*)d_in[5];
    const float* Wv   = (const float*)d_in[6];
    const float* Wo   = (const float*)d_in[7];
    float* out = (float*)d_out;

    float *gq, *gk, *gv, *gmh;
    cudaGetSymbolAddress((void**)&gq, g_Q);
    cudaGetSymbolAddress((void**)&gk, g_K);
    cudaGetSymbolAddress((void**)&gv, g_V);
    cudaGetSymbolAddress((void**)&gmh, g_MH);

    dim3 gg(DM_ / 128, M_ / 128);   // (8, 64)

    gemm_nt_kernel<<<gg, 256>>>(q, Wq, gq, 1);
    gemm_nt_kernel<<<gg, 256>>>(k, Wk, gk, 1);
    gemm_nt_kernel<<<gg, 256>>>(v, Wv, gv, 1);

    attn_kernel<<<dim3(S_ / 64, H_, B_), 256>>>(gq, gk, gv, mask, gmh);

    gemm_nt_kernel<<<gg, 256>>>(gmh, Wo, out, 0);
}

// round 4
// speedup vs baseline: 1.3567x; 1.3567x over previous
#include <cuda_runtime.h>
#include <cuda_bf16.h>
#include <cstdint>

#define B_ 4
#define S_ 2048
#define DM_ 1024
#define H_ 16
#define DK_ 64
#define M_ (B_ * S_)   // 8192

// Scratch (device globals; allocation-free per harness rules)
__device__ float g_Q[B_ * H_ * S_ * DK_];
__device__ float g_K[B_ * H_ * S_ * DK_];
__device__ float g_V[B_ * H_ * S_ * DK_];
__device__ float g_MH[B_ * S_ * DM_];
__device__ __nv_bfloat16 g_Ahi[M_ * DM_];
__device__ __nv_bfloat16 g_Alo[M_ * DM_];
__device__ __nv_bfloat16 g_Whi[DM_ * DM_];
__device__ __nv_bfloat16 g_Wlo[DM_ * DM_];

// ===========================================================================
// Base-ISA helpers (valid on sm_103 WITHOUT the 'a' feature set)
// ===========================================================================
__device__ __forceinline__ uint32_t smem_u32(const void* p) {
    uint32_t a;
    asm("{ .reg .u64 t; cvta.to.shared.u64 t, %1; cvt.u32.u64 %0, t; }"
        : "=r"(a) : "l"(p));
    return a;
}

__device__ __forceinline__ void ldsm4(uint32_t* r, uint32_t addr) {
    asm volatile("ldmatrix.sync.aligned.m8n8.x4.shared.b16 {%0,%1,%2,%3}, [%4];"
                 : "=r"(r[0]), "=r"(r[1]), "=r"(r[2]), "=r"(r[3]) : "r"(addr));
}

__device__ __forceinline__ void mma_bf16(float* d, const uint32_t* a, const uint32_t* b) {
    asm volatile(
        "mma.sync.aligned.m16n8k16.row.col.f32.bf16.bf16.f32 "
        "{%0,%1,%2,%3}, {%4,%5,%6,%7}, {%8,%9}, {%0,%1,%2,%3};"
        : "+f"(d[0]), "+f"(d[1]), "+f"(d[2]), "+f"(d[3])
        : "r"(a[0]), "r"(a[1]), "r"(a[2]), "r"(a[3]), "r"(b[0]), "r"(b[1]));
}

#define CP16(dst, src) \
    asm volatile("cp.async.cg.shared.global [%0], [%1], 16;" :: "r"(dst), "l"(src))
#define CP_COMMIT() asm volatile("cp.async.commit_group;" ::: "memory")
#define CP_WAIT0()  asm volatile("cp.async.wait_group 0;" ::: "memory")

// ===========================================================================
// Pre-split: fp32 -> bf16 hi/lo pair (3-term product error ~2^-16)
// one thread per float4
// ===========================================================================
__global__ __launch_bounds__(256) void split_kernel(
    const float* __restrict__ in,
    __nv_bfloat16* __restrict__ hi, __nv_bfloat16* __restrict__ lo)
{
    int i = blockIdx.x * blockDim.x + threadIdx.x;
    float4 v = reinterpret_cast<const float4*>(in)[i];
    __nv_bfloat162 h0, h1, l0, l1;
    h0.x = __float2bfloat16(v.x); h0.y = __float2bfloat16(v.y);
    h1.x = __float2bfloat16(v.z); h1.y = __float2bfloat16(v.w);
    l0.x = __float2bfloat16(v.x - __bfloat162float(h0.x));
    l0.y = __float2bfloat16(v.y - __bfloat162float(h0.y));
    l1.x = __float2bfloat16(v.z - __bfloat162float(h1.x));
    l1.y = __float2bfloat16(v.w - __bfloat162float(h1.y));
    reinterpret_cast<__nv_bfloat162*>(hi)[i * 2 + 0] = h0;
    reinterpret_cast<__nv_bfloat162*>(hi)[i * 2 + 1] = h1;
    reinterpret_cast<__nv_bfloat162*>(lo)[i * 2 + 0] = l0;
    reinterpret_cast<__nv_bfloat162*>(lo)[i * 2 + 1] = l1;
}

// ===========================================================================
// bf16 HMMA GEMM: C[m,n] = sum_k A[m,k]*W[n,k] with 3-term hi/lo split.
// CTA tile 128x128, BK=32, 2-stage cp.async pipeline, 8 warps (32x64 each).
// Smem rows padded to 80B -> conflict-free ldmatrix, no swizzle.
// ===========================================================================
#define ROWB   80
#define TILEB  (128 * ROWB)      // 10240 B per tile
#define STAGEB (4 * TILEB)       // Ahi, Alo, Bhi, Blo = 40960 B
#define SMEMG  (2 * STAGEB)      // 81920 B

__global__ __launch_bounds__(256, 2) void gemm_bf16_kernel(
    const __nv_bfloat16* __restrict__ Ahi, const __nv_bfloat16* __restrict__ Alo,
    const __nv_bfloat16* __restrict__ Bhi, const __nv_bfloat16* __restrict__ Blo,
    float* __restrict__ C, int headSplit)
{
    extern __shared__ char smg[];
    const uint32_t sbase = smem_u32(smg);
    const int tid  = threadIdx.x;
    const int lane = tid & 31;
    const int wid  = tid >> 5;
    const int wm   = (wid & 3) * 32;    // warp row offset within CTA tile
    const int wn   = (wid >> 2) * 64;   // warp col offset within CTA tile
    const int m0   = blockIdx.y * 128;
    const int n0   = blockIdx.x * 128;

    const __nv_bfloat16* gsrc[4] = {
        Ahi + (size_t)m0 * 1024, Alo + (size_t)m0 * 1024,
        Bhi + (size_t)n0 * 1024, Blo + (size_t)n0 * 1024 };

    float acc[2][8][4];
#pragma unroll
    for (int i = 0; i < 2; i++)
#pragma unroll
        for (int j = 0; j < 8; j++)
#pragma unroll
            for (int r = 0; r < 4; r++) acc[i][j][r] = 0.f;

    // issue one stage of cp.async loads (k-chunk c into buffer s)
    auto issue = [&](int c, int s) {
#pragma unroll
        for (int l = 0; l < 8; l++) {
            int T  = l >> 1;
            int q  = tid + (l & 1) * 256;          // 0..511 chunk id per tile
            int row = q >> 2, cc = q & 3;
            uint32_t dst = sbase + s * STAGEB + T * TILEB + row * ROWB + cc * 16;
            const __nv_bfloat16* src = gsrc[T] + (size_t)row * 1024 + c * 32 + cc * 8;
            CP16(dst, src);
        }
        CP_COMMIT();
    };

    issue(0, 0);

    // ldmatrix lane addressing (A: std x4; B: two n-tiles per x4)
    const int a_roff = (lane & 7) + ((lane >> 3) & 1) * 8;
    const int a_coff = ((lane >> 4) & 1) * 16;
    const int b_roff = (lane & 7) + ((lane >> 4) & 1) * 8;
    const int b_coff = ((lane >> 3) & 1) * 16;

    for (int c = 0; c < 32; c++) {
        const int s = c & 1;
        CP_WAIT0();
        __syncthreads();
        if (c < 31) issue(c + 1, s ^ 1);

        const uint32_t tA_hi = sbase + s * STAGEB;
        const uint32_t tA_lo = tA_hi + TILEB;
        const uint32_t tB_hi = tA_hi + 2 * TILEB;
        const uint32_t tB_lo = tA_hi + 3 * TILEB;

#pragma unroll
        for (int ks = 0; ks < 2; ks++) {
            uint32_t ah[2][4], al[2][4];
#pragma unroll
            for (int mt = 0; mt < 2; mt++) {
                uint32_t off = (uint32_t)(wm + mt * 16 + a_roff) * ROWB + ks * 32 + a_coff;
                ldsm4(ah[mt], tA_hi + off);
                ldsm4(al[mt], tA_lo + off);
            }
#pragma unroll
            for (int np = 0; np < 4; np++) {
                uint32_t bh[4], bl[4];
                uint32_t off = (uint32_t)(wn + np * 16 + b_roff) * ROWB + ks * 32 + b_coff;
                ldsm4(bh, tB_hi + off);
                ldsm4(bl, tB_lo + off);
#pragma unroll
                for (int mt = 0; mt < 2; mt++) {
#pragma unroll
                    for (int j = 0; j < 2; j++) {
                        float* d = acc[mt][np * 2 + j];
                        mma_bf16(d, ah[mt], bh + j * 2);
                        mma_bf16(d, ah[mt], bl + j * 2);
                        mma_bf16(d, al[mt], bh + j * 2);
                    }
                }
            }
        }
        __syncthreads();
    }

    // epilogue: d0,d1 -> (row = l/4, col = 2*(l%4)), d2,d3 -> row+8
#pragma unroll
    for (int mt = 0; mt < 2; mt++) {
#pragma unroll
        for (int nt = 0; nt < 8; nt++) {
            int row0 = m0 + wm + mt * 16 + (lane >> 2);
            int col  = n0 + wn + nt * 8 + (lane & 3) * 2;
            float2 v0 = make_float2(acc[mt][nt][0], acc[mt][nt][1]);
            float2 v1 = make_float2(acc[mt][nt][2], acc[mt][nt][3]);
            if (headSplit) {
                int h = col >> 6, dk = col & 63;
                int b0r = row0 >> 11, s0 = row0 & 2047;
                int b1r = (row0 + 8) >> 11, s1 = (row0 + 8) & 2047;
                *reinterpret_cast<float2*>(
                    &C[(((size_t)(b0r * H_ + h) * S_) + s0) * DK_ + dk]) = v0;
                *reinterpret_cast<float2*>(
                    &C[(((size_t)(b1r * H_ + h) * S_) + s1) * DK_ + dk]) = v1;
            } else {
                *reinterpret_cast<float2*>(&C[(size_t)row0 * 1024 + col]) = v0;
                *reinterpret_cast<float2*>(&C[(size_t)(row0 + 8) * 1024 + col]) = v1;
            }
        }
    }
}

// ---------------------------------------------------------------------------
// Flash attention, fp32 SIMT (unchanged from passing R1 kernel)
// ---------------------------------------------------------------------------
__global__ __launch_bounds__(256) void attn_kernel(
    const float* __restrict__ Qp, const float* __restrict__ Kp,
    const float* __restrict__ Vp, const int* __restrict__ mask,
    float* __restrict__ MH)
{
    __shared__ float Qs[64 * 64];
    __shared__ float KPs[64 * 64];
    __shared__ float Vs[64 * 64];

    const int tid = threadIdx.x;
    const int tx = tid & 15;
    const int ty = tid >> 4;
    const int qb = blockIdx.x;
    const int h  = blockIdx.y;
    const int b  = blockIdx.z;

    const float* Qbh = Qp + ((b * H_ + h) * S_) * DK_;
    const float* Kbh = Kp + ((b * H_ + h) * S_) * DK_;
    const float* Vbh = Vp + ((b * H_ + h) * S_) * DK_;
    const int* mrow = mask + b * S_;
    const int q0 = qb * 64;

#pragma unroll
    for (int i = 0; i < 4; i++) {
        int f   = tid + i * 256;
        int row = f >> 4;
        int c   = (f & 15) << 2;
        float4 v = *reinterpret_cast<const float4*>(Qbh + (q0 + row) * 64 + c);
        Qs[(c + 0) * 64 + row] = v.x * 0.125f;
        Qs[(c + 1) * 64 + row] = v.y * 0.125f;
        Qs[(c + 2) * 64 + row] = v.z * 0.125f;
        Qs[(c + 3) * 64 + row] = v.w * 0.125f;
    }

    float accO[4][4];
    float mr[4], lr[4];
#pragma unroll
    for (int i = 0; i < 4; i++) {
        mr[i] = -1e30f;
        lr[i] = 0.f;
#pragma unroll
        for (int j = 0; j < 4; j++) accO[i][j] = 0.f;
    }

    for (int kb = 0; kb < 32; kb++) {
        __syncthreads();

#pragma unroll
        for (int i = 0; i < 4; i++) {
            int f   = tid + i * 256;
            int row = f >> 4;
            int c   = (f & 15) << 2;
            float4 kv = *reinterpret_cast<const float4*>(Kbh + (kb * 64 + row) * 64 + c);
            KPs[(c + 0) * 64 + row] = kv.x;
            KPs[(c + 1) * 64 + row] = kv.y;
            KPs[(c + 2) * 64 + row] = kv.z;
            KPs[(c + 3) * 64 + row] = kv.w;
            float4 vv = *reinterpret_cast<const float4*>(Vbh + (kb * 64 + row) * 64 + c);
            *reinterpret_cast<float4*>(&Vs[row * 64 + c]) = vv;
        }
        __syncthreads();

        float s[4][4];
#pragma unroll
        for (int i = 0; i < 4; i++)
#pragma unroll
            for (int j = 0; j < 4; j++) s[i][j] = 0.f;

#pragma unroll 8
        for (int d = 0; d < 64; d++) {
            float4 a = *reinterpret_cast<const float4*>(&Qs[d * 64 + ty * 4]);
            float4 bb = *reinterpret_cast<const float4*>(&KPs[d * 64 + tx * 4]);
            float ra[4] = {a.x, a.y, a.z, a.w};
            float rb[4] = {bb.x, bb.y, bb.z, bb.w};
#pragma unroll
            for (int ii = 0; ii < 4; ii++)
#pragma unroll
                for (int jj = 0; jj < 4; jj++)
                    s[ii][jj] = fmaf(ra[ii], rb[jj], s[ii][jj]);
        }

#pragma unroll
        for (int jj = 0; jj < 4; jj++) {
            int mv = mrow[kb * 64 + tx * 4 + jj];
            if (mv == 0) {
#pragma unroll
                for (int ii = 0; ii < 4; ii++) s[ii][jj] = -1e9f;
            }
        }

        float alpha[4];
#pragma unroll
        for (int ii = 0; ii < 4; ii++) {
            float rmax = fmaxf(fmaxf(s[ii][0], s[ii][1]), fmaxf(s[ii][2], s[ii][3]));
#pragma unroll
            for (int o = 8; o >= 1; o >>= 1)
                rmax = fmaxf(rmax, __shfl_xor_sync(0xffffffffu, rmax, o));
            float mn = fmaxf(mr[ii], rmax);
            alpha[ii] = __expf(mr[ii] - mn);
            mr[ii] = mn;
            float rsum = 0.f;
#pragma unroll
            for (int jj = 0; jj < 4; jj++) {
                s[ii][jj] = __expf(s[ii][jj] - mn);
                rsum += s[ii][jj];
            }
#pragma unroll
            for (int o = 8; o >= 1; o >>= 1)
                rsum += __shfl_xor_sync(0xffffffffu, rsum, o);
            lr[ii] = lr[ii] * alpha[ii] + rsum;
#pragma unroll
            for (int jj = 0; jj < 4; jj++) accO[ii][jj] *= alpha[ii];
        }

        __syncthreads();
#pragma unroll
        for (int ii = 0; ii < 4; ii++) {
            float4 p = make_float4(s[ii][0], s[ii][1], s[ii][2], s[ii][3]);
            *reinterpret_cast<float4*>(&KPs[(ty * 4 + ii) * 64 + tx * 4]) = p;
        }
        __syncthreads();

#pragma unroll 8
        for (int j = 0; j < 64; j++) {
            float4 vv = *reinterpret_cast<const float4*>(&Vs[j * 64 + tx * 4]);
            float rv[4] = {vv.x, vv.y, vv.z, vv.w};
            float rp[4];
#pragma unroll
            for (int ii = 0; ii < 4; ii++) rp[ii] = KPs[(ty * 4 + ii) * 64 + j];
#pragma unroll
            for (int ii = 0; ii < 4; ii++)
#pragma unroll
                for (int jj = 0; jj < 4; jj++)
                    accO[ii][jj] = fmaf(rp[ii], rv[jj], accO[ii][jj]);
        }
    }

#pragma unroll
    for (int ii = 0; ii < 4; ii++) {
        float inv = 1.f / lr[ii];
        int srow = q0 + ty * 4 + ii;
        float4 o = make_float4(accO[ii][0] * inv, accO[ii][1] * inv,
                               accO[ii][2] * inv, accO[ii][3] * inv);
        *reinterpret_cast<float4*>(&MH[(b * S_ + srow) * DM_ + h * 64 + tx * 4]) = o;
    }
}

// ---------------------------------------------------------------------------
extern "C" void kernel_launch(void* const* d_in, const int* in_sizes, int n_in,
                              void* d_out, int out_size)
{
    const float* q    = (const float*)d_in[0];
    const float* k    = (const float*)d_in[1];
    const float* v    = (const float*)d_in[2];
    const int*   mask = (const int*)d_in[3];
    const float* Wq   = (const float*)d_in[4];
    const float* Wk   = (const float*)d_in[5];
    const float* Wv   = (const float*)d_in[6];
    const float* Wo   = (const float*)d_in[7];
    float* out = (float*)d_out;

    float *gq, *gk, *gv, *gmh;
    __nv_bfloat16 *ahi, *alo, *whi, *wlo;
    cudaGetSymbolAddress((void**)&gq, g_Q);
    cudaGetSymbolAddress((void**)&gk, g_K);
    cudaGetSymbolAddress((void**)&gv, g_V);
    cudaGetSymbolAddress((void**)&gmh, g_MH);
    cudaGetSymbolAddress((void**)&ahi, g_Ahi);
    cudaGetSymbolAddress((void**)&alo, g_Alo);
    cudaGetSymbolAddress((void**)&whi, g_Whi);
    cudaGetSymbolAddress((void**)&wlo, g_Wlo);

    cudaFuncSetAttribute(gemm_bf16_kernel,
                         cudaFuncAttributeMaxDynamicSharedMemorySize, SMEMG);

    const int nA4 = M_ * DM_ / 4;    // float4 count for activations
    const int nW4 = DM_ * DM_ / 4;   // float4 count for weights
    dim3 gg(DM_ / 128, M_ / 128);    // (8, 64)

    // Q projection
    split_kernel<<<nA4 / 256, 256>>>(q, ahi, alo);
    split_kernel<<<nW4 / 256, 256>>>(Wq, whi, wlo);
    gemm_bf16_kernel<<<gg, 256, SMEMG>>>(ahi, alo, whi, wlo, gq, 1);
    // K projection
    split_kernel<<<nA4 / 256, 256>>>(k, ahi, alo);
    split_kernel<<<nW4 / 256, 256>>>(Wk, whi, wlo);
    gemm_bf16_kernel<<<gg, 256, SMEMG>>>(ahi, alo, whi, wlo, gk, 1);
    // V projection
    split_kernel<<<nA4 / 256, 256>>>(v, ahi, alo);
    split_kernel<<<nW4 / 256, 256>>>(Wv, whi, wlo);
    gemm_bf16_kernel<<<gg, 256, SMEMG>>>(ahi, alo, whi, wlo, gv, 1);

    // attention
    attn_kernel<<<dim3(S_ / 64, H_, B_), 256>>>(gq, gk, gv, mask, gmh);

    // output projection
    split_kernel<<<nA4 / 256, 256>>>(gmh, ahi, alo);
    split_kernel<<<nW4 / 256, 256>>>(Wo, whi, wlo);
    gemm_bf16_kernel<<<gg, 256, SMEMG>>>(ahi, alo, whi, wlo, out, 0);
}

// round 5
// speedup vs baseline: 3.1553x; 2.3256x over previous
#include <cuda_runtime.h>
#include <cuda_bf16.h>
#include <cstdint>

#define B_ 4
#define S_ 2048
#define DM_ 1024
#define H_ 16
#define DK_ 64
#define M_ (B_ * S_)   // 8192

// Scratch (device globals; allocation-free per harness rules)
__device__ __nv_bfloat16 g_Ahi[M_ * DM_];
__device__ __nv_bfloat16 g_Alo[M_ * DM_];
__device__ __nv_bfloat16 g_Whi[DM_ * DM_];
__device__ __nv_bfloat16 g_Wlo[DM_ * DM_];
__device__ __nv_bfloat16 g_Qhi[B_ * H_ * S_ * DK_];
__device__ __nv_bfloat16 g_Qlo[B_ * H_ * S_ * DK_];
__device__ __nv_bfloat16 g_Khi[B_ * H_ * S_ * DK_];
__device__ __nv_bfloat16 g_Klo[B_ * H_ * S_ * DK_];
__device__ __nv_bfloat16 g_Vhi[B_ * H_ * S_ * DK_];
__device__ __nv_bfloat16 g_Vlo[B_ * H_ * S_ * DK_];

// ===========================================================================
// Base-ISA helpers (valid on sm_103 WITHOUT the 'a' feature set)
// ===========================================================================
__device__ __forceinline__ uint32_t smem_u32(const void* p) {
    uint32_t a;
    asm("{ .reg .u64 t; cvta.to.shared.u64 t, %1; cvt.u32.u64 %0, t; }"
        : "=r"(a) : "l"(p));
    return a;
}
__device__ __forceinline__ void ldsm4(uint32_t* r, uint32_t addr) {
    asm volatile("ldmatrix.sync.aligned.m8n8.x4.shared.b16 {%0,%1,%2,%3}, [%4];"
                 : "=r"(r[0]), "=r"(r[1]), "=r"(r[2]), "=r"(r[3]) : "r"(addr));
}
__device__ __forceinline__ void ldsm4t(uint32_t* r, uint32_t addr) {
    asm volatile("ldmatrix.sync.aligned.m8n8.x4.trans.shared.b16 {%0,%1,%2,%3}, [%4];"
                 : "=r"(r[0]), "=r"(r[1]), "=r"(r[2]), "=r"(r[3]) : "r"(addr));
}
__device__ __forceinline__ void mma_bf16(float* d, const uint32_t* a, const uint32_t* b) {
    asm volatile(
        "mma.sync.aligned.m16n8k16.row.col.f32.bf16.bf16.f32 "
        "{%0,%1,%2,%3}, {%4,%5,%6,%7}, {%8,%9}, {%0,%1,%2,%3};"
        : "+f"(d[0]), "+f"(d[1]), "+f"(d[2]), "+f"(d[3])
        : "r"(a[0]), "r"(a[1]), "r"(a[2]), "r"(a[3]), "r"(b[0]), "r"(b[1]));
}
#define CP16(dst, src) \
    asm volatile("cp.async.cg.shared.global [%0], [%1], 16;" :: "r"(dst), "l"(src))
#define CP_COMMIT() asm volatile("cp.async.commit_group;" ::: "memory")
#define CP_WAIT0()  asm volatile("cp.async.wait_group 0;" ::: "memory")
#define CP_WAIT1()  asm volatile("cp.async.wait_group 1;" ::: "memory")

// split f32 pair -> bf16x2 hi + bf16x2 lo (packed u32)
__device__ __forceinline__ void split2(float a, float b, uint32_t& hi, uint32_t& lo) {
    __nv_bfloat162 h, l;
    h.x = __float2bfloat16(a); h.y = __float2bfloat16(b);
    l.x = __float2bfloat16(a - __bfloat162float(h.x));
    l.y = __float2bfloat16(b - __bfloat162float(h.y));
    hi = *reinterpret_cast<uint32_t*>(&h);
    lo = *reinterpret_cast<uint32_t*>(&l);
}

// ===========================================================================
// Pre-split: fp32 -> bf16 hi/lo pair
// ===========================================================================
__global__ __launch_bounds__(256) void split_kernel(
    const float* __restrict__ in,
    __nv_bfloat16* __restrict__ hi, __nv_bfloat16* __restrict__ lo)
{
    int i = blockIdx.x * blockDim.x + threadIdx.x;
    float4 v = reinterpret_cast<const float4*>(in)[i];
    uint32_t h0, h1, l0, l1;
    split2(v.x, v.y, h0, l0);
    split2(v.z, v.w, h1, l1);
    reinterpret_cast<uint32_t*>(hi)[i * 2 + 0] = h0;
    reinterpret_cast<uint32_t*>(hi)[i * 2 + 1] = h1;
    reinterpret_cast<uint32_t*>(lo)[i * 2 + 0] = l0;
    reinterpret_cast<uint32_t*>(lo)[i * 2 + 1] = l1;
}

// ===========================================================================
// bf16 HMMA GEMM: C[m,n] = sum_k A[m,k]*W[n,k] with 3-term hi/lo split.
// mode 0: Cf fp32 [m][1024].
// mode 1: Chi/Clo bf16 split, head layout [b,h,s,dk], scaled by `scale`.
// ===========================================================================
#define ROWB   80
#define TILEB  (128 * ROWB)
#define STAGEB (4 * TILEB)
#define SMEMG  (2 * STAGEB)      // 81920 B

__global__ __launch_bounds__(256, 2) void gemm_bf16_kernel(
    const __nv_bfloat16* __restrict__ Ahi, const __nv_bfloat16* __restrict__ Alo,
    const __nv_bfloat16* __restrict__ Bhi, const __nv_bfloat16* __restrict__ Blo,
    float* __restrict__ Cf,
    __nv_bfloat16* __restrict__ Chi, __nv_bfloat16* __restrict__ Clo,
    int mode, float scale)
{
    extern __shared__ char smg[];
    const uint32_t sbase = smem_u32(smg);
    const int tid  = threadIdx.x;
    const int lane = tid & 31;
    const int wid  = tid >> 5;
    const int wm   = (wid & 3) * 32;
    const int wn   = (wid >> 2) * 64;
    const int m0   = blockIdx.y * 128;
    const int n0   = blockIdx.x * 128;

    const __nv_bfloat16* gsrc[4] = {
        Ahi + (size_t)m0 * 1024, Alo + (size_t)m0 * 1024,
        Bhi + (size_t)n0 * 1024, Blo + (size_t)n0 * 1024 };

    float acc[2][8][4];
#pragma unroll
    for (int i = 0; i < 2; i++)
#pragma unroll
        for (int j = 0; j < 8; j++)
#pragma unroll
            for (int r = 0; r < 4; r++) acc[i][j][r] = 0.f;

    auto issue = [&](int c, int s) {
#pragma unroll
        for (int l = 0; l < 8; l++) {
            int T  = l >> 1;
            int q  = tid + (l & 1) * 256;
            int row = q >> 2, cc = q & 3;
            uint32_t dst = sbase + s * STAGEB + T * TILEB + row * ROWB + cc * 16;
            const __nv_bfloat16* src = gsrc[T] + (size_t)row * 1024 + c * 32 + cc * 8;
            CP16(dst, src);
        }
        CP_COMMIT();
    };

    issue(0, 0);

    const int a_roff = (lane & 7) + ((lane >> 3) & 1) * 8;
    const int a_coff = ((lane >> 4) & 1) * 16;
    const int b_roff = (lane & 7) + ((lane >> 4) & 1) * 8;
    const int b_coff = ((lane >> 3) & 1) * 16;

    for (int c = 0; c < 32; c++) {
        const int s = c & 1;
        CP_WAIT0();
        __syncthreads();
        if (c < 31) issue(c + 1, s ^ 1);

        const uint32_t tA_hi = sbase + s * STAGEB;
        const uint32_t tA_lo = tA_hi + TILEB;
        const uint32_t tB_hi = tA_hi + 2 * TILEB;
        const uint32_t tB_lo = tA_hi + 3 * TILEB;

#pragma unroll
        for (int ks = 0; ks < 2; ks++) {
            uint32_t ah[2][4], al[2][4];
#pragma unroll
            for (int mt = 0; mt < 2; mt++) {
                uint32_t off = (uint32_t)(wm + mt * 16 + a_roff) * ROWB + ks * 32 + a_coff;
                ldsm4(ah[mt], tA_hi + off);
                ldsm4(al[mt], tA_lo + off);
            }
#pragma unroll
            for (int np = 0; np < 4; np++) {
                uint32_t bh[4], bl[4];
                uint32_t off = (uint32_t)(wn + np * 16 + b_roff) * ROWB + ks * 32 + b_coff;
                ldsm4(bh, tB_hi + off);
                ldsm4(bl, tB_lo + off);
#pragma unroll
                for (int mt = 0; mt < 2; mt++) {
#pragma unroll
                    for (int j = 0; j < 2; j++) {
                        float* d = acc[mt][np * 2 + j];
                        mma_bf16(d, ah[mt], bh + j * 2);
                        mma_bf16(d, ah[mt], bl + j * 2);
                        mma_bf16(d, al[mt], bh + j * 2);
                    }
                }
            }
        }
        __syncthreads();
    }

#pragma unroll
    for (int mt = 0; mt < 2; mt++) {
#pragma unroll
        for (int nt = 0; nt < 8; nt++) {
            int row0 = m0 + wm + mt * 16 + (lane >> 2);
            int col  = n0 + wn + nt * 8 + (lane & 3) * 2;
            float2 v0 = make_float2(acc[mt][nt][0], acc[mt][nt][1]);
            float2 v1 = make_float2(acc[mt][nt][2], acc[mt][nt][3]);
            if (mode == 1) {
                int h = col >> 6, dk = col & 63;
#pragma unroll
                for (int rr = 0; rr < 2; rr++) {
                    int row = row0 + rr * 8;
                    float2 v = rr ? v1 : v0;
                    size_t idx = (((size_t)((row >> 11) * H_ + h) * S_) + (row & 2047)) * DK_ + dk;
                    uint32_t hi, lo;
                    split2(v.x * scale, v.y * scale, hi, lo);
                    *reinterpret_cast<uint32_t*>(Chi + idx) = hi;
                    *reinterpret_cast<uint32_t*>(Clo + idx) = lo;
                }
            } else {
                *reinterpret_cast<float2*>(&Cf[(size_t)row0 * 1024 + col]) = v0;
                *reinterpret_cast<float2*>(&Cf[(size_t)(row0 + 8) * 1024 + col]) = v1;
            }
        }
    }
}

// ===========================================================================
// Flash attention on HMMA, 3-term bf16 split.
// CTA: 128 q-rows x full key loop (64-key blocks). 8 warps, 16 q-rows each.
// Q/K: [row][dk] bf16 hi/lo (Q pre-scaled by 1/8). V natural [key][dk] via
// ldmatrix.trans. Output written as bf16 hi/lo split into Ahi/Alo [m][1024].
// ===========================================================================
#define AROW 144
#define QOFF 0              // 2 * 128*144 = 36864
#define KOFF 36864          // 2 bufs * 2 (hi/lo) * 64*144 = 36864
#define VOFF 73728
#define MOFF 110592         // 2 * 256
#define ASMEM 111104

__global__ __launch_bounds__(256, 2) void attn_mma_kernel(
    const __nv_bfloat16* __restrict__ Qhi, const __nv_bfloat16* __restrict__ Qlo,
    const __nv_bfloat16* __restrict__ Khi, const __nv_bfloat16* __restrict__ Klo,
    const __nv_bfloat16* __restrict__ Vhi, const __nv_bfloat16* __restrict__ Vlo,
    const int* __restrict__ mask,
    __nv_bfloat16* __restrict__ Ohi, __nv_bfloat16* __restrict__ Olo)
{
    extern __shared__ char sma[];
    const uint32_t sbase = smem_u32(sma);
    const int tid  = threadIdx.x;
    const int lane = tid & 31;
    const int wid  = tid >> 5;
    const int wq   = wid * 16;          // warp's q-row offset in CTA tile
    const int q0   = blockIdx.x * 128;
    const int h    = blockIdx.y;
    const int b    = blockIdx.z;

    const size_t bh = ((size_t)b * H_ + h) * S_ * DK_;
    const __nv_bfloat16* Qhi_b = Qhi + bh;
    const __nv_bfloat16* Qlo_b = Qlo + bh;
    const __nv_bfloat16* Khi_b = Khi + bh;
    const __nv_bfloat16* Klo_b = Klo + bh;
    const __nv_bfloat16* Vhi_b = Vhi + bh;
    const __nv_bfloat16* Vlo_b = Vlo + bh;
    const int* mrow = mask + b * S_;

    // ---- prologue: Q tile (once) + K/V/mask block 0 ----
#pragma unroll
    for (int i = 0; i < 8; i++) {
        int c = tid + i * 256;             // 0..2047
        int T = c >> 10;
        int idx = c & 1023;
        int row = idx >> 3, ch = idx & 7;
        uint32_t dst = sbase + QOFF + T * 18432 + row * AROW + ch * 16;
        const __nv_bfloat16* src = (T ? Qlo_b : Qhi_b) + (size_t)(q0 + row) * 64 + ch * 8;
        CP16(dst, src);
    }
    auto issueKV = [&](int kb, int s) {
#pragma unroll
        for (int i = 0; i < 4; i++) {
            int c = tid + i * 256;         // 0..1023
            int T = c >> 9;
            int idx = c & 511;
            int row = idx >> 3, ch = idx & 7;
            uint32_t doff = s * 9216 + T * 18432 + (uint32_t)row * AROW + ch * 16;
            size_t soff = (size_t)(kb * 64 + row) * 64 + ch * 8;
            CP16(sbase + KOFF + doff, (T ? Klo_b : Khi_b) + soff);
            CP16(sbase + VOFF + doff, (T ? Vlo_b : Vhi_b) + soff);
        }
        if (tid < 16)
            CP16(sbase + MOFF + s * 256 + tid * 16, mrow + kb * 64 + tid * 4);
    };
    issueKV(0, 0);
    CP_COMMIT();

    // fragment addressing
    const int a_roff  = (lane & 7) + ((lane >> 3) & 1) * 8;
    const int a_coff  = ((lane >> 4) & 1) * 16;
    const int b_roff  = (lane & 7) + ((lane >> 4) & 1) * 8;
    const int b_coff  = ((lane >> 3) & 1) * 16;
    const int vb_roff = (lane & 7) + ((lane >> 3) & 1) * 8;   // key within chunk
    const int vb_coff = ((lane >> 4) & 1) * 16;               // dk bytes

    float O[8][4];
#pragma unroll
    for (int i = 0; i < 8; i++)
#pragma unroll
        for (int j = 0; j < 4; j++) O[i][j] = 0.f;
    float mM[2] = {-1e30f, -1e30f};
    float lL[2] = {0.f, 0.f};

    for (int kb = 0; kb < 32; kb++) {
        const int s = kb & 1;
        if (kb < 31) { issueKV(kb + 1, s ^ 1); CP_COMMIT(); CP_WAIT1(); }
        else         { CP_WAIT0(); }
        __syncthreads();

        // ---- scores = Q @ K^T (pre-scaled) ----
        float sc[8][4];
#pragma unroll
        for (int i = 0; i < 8; i++)
#pragma unroll
            for (int j = 0; j < 4; j++) sc[i][j] = 0.f;

        const uint32_t kb_hi = sbase + KOFF + s * 9216;
        const uint32_t kb_lo = kb_hi + 18432;
#pragma unroll
        for (int ks = 0; ks < 4; ks++) {
            uint32_t ah[4], al[4];
            uint32_t aoff = (uint32_t)(wq + a_roff) * AROW + ks * 32 + a_coff;
            ldsm4(ah, sbase + QOFF + aoff);
            ldsm4(al, sbase + QOFF + 18432 + aoff);
#pragma unroll
            for (int np = 0; np < 4; np++) {
                uint32_t bh2[4], bl2[4];
                uint32_t boff = (uint32_t)(np * 16 + b_roff) * AROW + ks * 32 + b_coff;
                ldsm4(bh2, kb_hi + boff);
                ldsm4(bl2, kb_lo + boff);
#pragma unroll
                for (int j = 0; j < 2; j++) {
                    float* d = sc[np * 2 + j];
                    mma_bf16(d, ah, bh2 + j * 2);
                    mma_bf16(d, ah, bl2 + j * 2);
                    mma_bf16(d, al, bh2 + j * 2);
                }
            }
        }

        // ---- mask ----
        const int c0 = (lane & 3) * 2;
#pragma unroll
        for (int st = 0; st < 8; st++) {
            int2 mv = *reinterpret_cast<const int2*>(
                sma + (MOFF + s * 256) + (st * 8 + c0) * 4);
            if (mv.x == 0) { sc[st][0] = -1e9f; sc[st][2] = -1e9f; }
            if (mv.y == 0) { sc[st][1] = -1e9f; sc[st][3] = -1e9f; }
        }

        // ---- online softmax (2 rows per thread: r, r+8) ----
        float alpha[2];
#pragma unroll
        for (int rh = 0; rh < 2; rh++) {
            float mx = -1e30f;
#pragma unroll
            for (int st = 0; st < 8; st++)
                mx = fmaxf(mx, fmaxf(sc[st][rh * 2], sc[st][rh * 2 + 1]));
            mx = fmaxf(mx, __shfl_xor_sync(0xffffffffu, mx, 1));
            mx = fmaxf(mx, __shfl_xor_sync(0xffffffffu, mx, 2));
            float mn = fmaxf(mM[rh], mx);
            alpha[rh] = __expf(mM[rh] - mn);
            mM[rh] = mn;
            float rsum = 0.f;
#pragma unroll
            for (int st = 0; st < 8; st++) {
                float p0 = __expf(sc[st][rh * 2] - mn);
                float p1 = __expf(sc[st][rh * 2 + 1] - mn);
                sc[st][rh * 2] = p0; sc[st][rh * 2 + 1] = p1;
                rsum += p0 + p1;
            }
            rsum += __shfl_xor_sync(0xffffffffu, rsum, 1);
            rsum += __shfl_xor_sync(0xffffffffu, rsum, 2);
            lL[rh] = lL[rh] * alpha[rh] + rsum;
        }
#pragma unroll
        for (int nt = 0; nt < 8; nt++) {
            O[nt][0] *= alpha[0]; O[nt][1] *= alpha[0];
            O[nt][2] *= alpha[1]; O[nt][3] *= alpha[1];
        }

        // ---- O += P @ V (P from registers, V via ldmatrix.trans) ----
        const uint32_t vb_hi = sbase + VOFF + s * 9216;
        const uint32_t vb_lo = vb_hi + 18432;
#pragma unroll
        for (int ks = 0; ks < 4; ks++) {   // 16-key chunks
            uint32_t ph[4], pl[4];
            split2(sc[2 * ks][0],     sc[2 * ks][1],     ph[0], pl[0]);
            split2(sc[2 * ks][2],     sc[2 * ks][3],     ph[1], pl[1]);
            split2(sc[2 * ks + 1][0], sc[2 * ks + 1][1], ph[2], pl[2]);
            split2(sc[2 * ks + 1][2], sc[2 * ks + 1][3], ph[3], pl[3]);
#pragma unroll
            for (int np = 0; np < 4; np++) {  // 16-dk chunks
                uint32_t vh[4], vl[4];
                uint32_t voff = (uint32_t)(ks * 16 + vb_roff) * AROW + np * 32 + vb_coff;
                ldsm4t(vh, vb_hi + voff);
                ldsm4t(vl, vb_lo + voff);
#pragma unroll
                for (int j = 0; j < 2; j++) {
                    float* d = O[np * 2 + j];
                    mma_bf16(d, ph, vh + j * 2);
                    mma_bf16(d, ph, vl + j * 2);
                    mma_bf16(d, pl, vh + j * 2);
                }
            }
        }
        __syncthreads();
    }

    // ---- epilogue: O /= l, write bf16 hi/lo into [m][1024] ----
#pragma unroll
    for (int rh = 0; rh < 2; rh++) {
        float inv = 1.f / lL[rh];
        int row = q0 + wq + (lane >> 2) + rh * 8;
        size_t mrow_o = ((size_t)b * S_ + row) * DM_ + h * 64;
#pragma unroll
        for (int nt = 0; nt < 8; nt++) {
            int col = nt * 8 + (lane & 3) * 2;
            uint32_t hi, lo;
            split2(O[nt][rh * 2] * inv, O[nt][rh * 2 + 1] * inv, hi, lo);
            *reinterpret_cast<uint32_t*>(Ohi + mrow_o + col) = hi;
            *reinterpret_cast<uint32_t*>(Olo + mrow_o + col) = lo;
        }
    }
}

// ---------------------------------------------------------------------------
extern "C" void kernel_launch(void* const* d_in, const int* in_sizes, int n_in,
                              void* d_out, int out_size)
{
    const float* q    = (const float*)d_in[0];
    const float* k    = (const float*)d_in[1];
    const float* v    = (const float*)d_in[2];
    const int*   mask = (const int*)d_in[3];
    const float* Wq   = (const float*)d_in[4];
    const float* Wk   = (const float*)d_in[5];
    const float* Wv   = (const float*)d_in[6];
    const float* Wo   = (const float*)d_in[7];
    float* out = (float*)d_out;

    __nv_bfloat16 *ahi, *alo, *whi, *wlo, *qhi, *qlo, *khi, *klo, *vhi, *vlo;
    cudaGetSymbolAddress((void**)&ahi, g_Ahi);
    cudaGetSymbolAddress((void**)&alo, g_Alo);
    cudaGetSymbolAddress((void**)&whi, g_Whi);
    cudaGetSymbolAddress((void**)&wlo, g_Wlo);
    cudaGetSymbolAddress((void**)&qhi, g_Qhi);
    cudaGetSymbolAddress((void**)&qlo, g_Qlo);
    cudaGetSymbolAddress((void**)&khi, g_Khi);
    cudaGetSymbolAddress((void**)&klo, g_Klo);
    cudaGetSymbolAddress((void**)&vhi, g_Vhi);
    cudaGetSymbolAddress((void**)&vlo, g_Vlo);

    cudaFuncSetAttribute(gemm_bf16_kernel,
                         cudaFuncAttributeMaxDynamicSharedMemorySize, SMEMG);
    cudaFuncSetAttribute(attn_mma_kernel,
                         cudaFuncAttributeMaxDynamicSharedMemorySize, ASMEM);

    const int nA4 = M_ * DM_ / 4;
    const int nW4 = DM_ * DM_ / 4;
    dim3 gg(DM_ / 128, M_ / 128);

    // Q projection (pre-scale by 1/sqrt(dk) = 0.125)
    split_kernel<<<nA4 / 256, 256>>>(q, ahi, alo);
    split_kernel<<<nW4 / 256, 256>>>(Wq, whi, wlo);
    gemm_bf16_kernel<<<gg, 256, SMEMG>>>(ahi, alo, whi, wlo, nullptr, qhi, qlo, 1, 0.125f);
    // K projection
    split_kernel<<<nA4 / 256, 256>>>(k, ahi, alo);
    split_kernel<<<nW4 / 256, 256>>>(Wk, whi, wlo);
    gemm_bf16_kernel<<<gg, 256, SMEMG>>>(ahi, alo, whi, wlo, nullptr, khi, klo, 1, 1.0f);
    // V projection
    split_kernel<<<nA4 / 256, 256>>>(v, ahi, alo);
    split_kernel<<<nW4 / 256, 256>>>(Wv, whi, wlo);
    gemm_bf16_kernel<<<gg, 256, SMEMG>>>(ahi, alo, whi, wlo, nullptr, vhi, vlo, 1, 1.0f);

    // attention (writes bf16 hi/lo merged-head output into ahi/alo)
    attn_mma_kernel<<<dim3(S_ / 128, H_, B_), 256, ASMEM>>>(
        qhi, qlo, khi, klo, vhi, vlo, mask, ahi, alo);

    // output projection (fp32 result)
    split_kernel<<<nW4 / 256, 256>>>(Wo, whi, wlo);
    gemm_bf16_kernel<<<gg, 256, SMEMG>>>(ahi, alo, whi, wlo, out, nullptr, nullptr, 0, 1.0f);
}

// round 6
// speedup vs baseline: 3.1649x; 1.0030x over previous
#include <cuda_runtime.h>
#include <cuda_bf16.h>
#include <cstdint>

#define B_ 4
#define S_ 2048
#define DM_ 1024
#define H_ 16
#define DK_ 64
#define M_ (B_ * S_)   // 8192

// Scratch (device globals; allocation-free per harness rules)
__device__ __nv_bfloat16 g_Ahi[M_ * DM_];
__device__ __nv_bfloat16 g_Alo[M_ * DM_];
__device__ __nv_bfloat16 g_Whi[DM_ * DM_];
__device__ __nv_bfloat16 g_Wlo[DM_ * DM_];
__device__ __nv_bfloat16 g_Qhi[B_ * H_ * S_ * DK_];
__device__ __nv_bfloat16 g_Qlo[B_ * H_ * S_ * DK_];
__device__ __nv_bfloat16 g_Khi[B_ * H_ * S_ * DK_];
__device__ __nv_bfloat16 g_Klo[B_ * H_ * S_ * DK_];
__device__ __nv_bfloat16 g_Vhi[B_ * H_ * S_ * DK_];
__device__ __nv_bfloat16 g_Vlo[B_ * H_ * S_ * DK_];

// ===========================================================================
// Base-ISA helpers (valid on sm_103 WITHOUT the 'a' feature set)
// ===========================================================================
__device__ __forceinline__ uint32_t smem_u32(const void* p) {
    uint32_t a;
    asm("{ .reg .u64 t; cvta.to.shared.u64 t, %1; cvt.u32.u64 %0, t; }"
        : "=r"(a) : "l"(p));
    return a;
}
__device__ __forceinline__ void ldsm4(uint32_t* r, uint32_t addr) {
    asm volatile("ldmatrix.sync.aligned.m8n8.x4.shared.b16 {%0,%1,%2,%3}, [%4];"
                 : "=r"(r[0]), "=r"(r[1]), "=r"(r[2]), "=r"(r[3]) : "r"(addr));
}
__device__ __forceinline__ void ldsm4t(uint32_t* r, uint32_t addr) {
    asm volatile("ldmatrix.sync.aligned.m8n8.x4.trans.shared.b16 {%0,%1,%2,%3}, [%4];"
                 : "=r"(r[0]), "=r"(r[1]), "=r"(r[2]), "=r"(r[3]) : "r"(addr));
}
__device__ __forceinline__ void mma_bf16(float* d, const uint32_t* a, const uint32_t* b) {
    asm volatile(
        "mma.sync.aligned.m16n8k16.row.col.f32.bf16.bf16.f32 "
        "{%0,%1,%2,%3}, {%4,%5,%6,%7}, {%8,%9}, {%0,%1,%2,%3};"
        : "+f"(d[0]), "+f"(d[1]), "+f"(d[2]), "+f"(d[3])
        : "r"(a[0]), "r"(a[1]), "r"(a[2]), "r"(a[3]), "r"(b[0]), "r"(b[1]));
}
#define CP16(dst, src) \
    asm volatile("cp.async.cg.shared.global [%0], [%1], 16;" :: "r"(dst), "l"(src))
#define CP_COMMIT() asm volatile("cp.async.commit_group;" ::: "memory")
#define CP_WAIT0()  asm volatile("cp.async.wait_group 0;" ::: "memory")
#define CP_WAIT1()  asm volatile("cp.async.wait_group 1;" ::: "memory")

// split f32 pair -> bf16x2 hi + bf16x2 lo (packed u32)
__device__ __forceinline__ void split2(float a, float b, uint32_t& hi, uint32_t& lo) {
    __nv_bfloat162 h, l;
    h.x = __float2bfloat16(a); h.y = __float2bfloat16(b);
    l.x = __float2bfloat16(a - __bfloat162float(h.x));
    l.y = __float2bfloat16(b - __bfloat162float(h.y));
    hi = *reinterpret_cast<uint32_t*>(&h);
    lo = *reinterpret_cast<uint32_t*>(&l);
}

// ===========================================================================
// Pre-split: fp32 -> bf16 hi/lo pair
// ===========================================================================
__global__ __launch_bounds__(256) void split_kernel(
    const float* __restrict__ in,
    __nv_bfloat16* __restrict__ hi, __nv_bfloat16* __restrict__ lo)
{
    int i = blockIdx.x * blockDim.x + threadIdx.x;
    float4 v = reinterpret_cast<const float4*>(in)[i];
    uint32_t h0, h1, l0, l1;
    split2(v.x, v.y, h0, l0);
    split2(v.z, v.w, h1, l1);
    reinterpret_cast<uint32_t*>(hi)[i * 2 + 0] = h0;
    reinterpret_cast<uint32_t*>(hi)[i * 2 + 1] = h1;
    reinterpret_cast<uint32_t*>(lo)[i * 2 + 0] = l0;
    reinterpret_cast<uint32_t*>(lo)[i * 2 + 1] = l1;
}

// ===========================================================================
// bf16 HMMA GEMM: C[m,n] = sum_k A[m,k]*W[n,k] with 3-term hi/lo split.
// mode 0: Cf fp32 [m][1024].
// mode 1: Chi/Clo bf16 split, head layout [b,h,s,dk], scaled by `scale`.
// ===========================================================================
#define ROWB   80
#define TILEB  (128 * ROWB)
#define STAGEB (4 * TILEB)
#define SMEMG  (2 * STAGEB)      // 81920 B

__global__ __launch_bounds__(256, 2) void gemm_bf16_kernel(
    const __nv_bfloat16* __restrict__ Ahi, const __nv_bfloat16* __restrict__ Alo,
    const __nv_bfloat16* __restrict__ Bhi, const __nv_bfloat16* __restrict__ Blo,
    float* __restrict__ Cf,
    __nv_bfloat16* __restrict__ Chi, __nv_bfloat16* __restrict__ Clo,
    int mode, float scale)
{
    extern __shared__ char smg[];
    const uint32_t sbase = smem_u32(smg);
    const int tid  = threadIdx.x;
    const int lane = tid & 31;
    const int wid  = tid >> 5;
    const int wm   = (wid & 3) * 32;
    const int wn   = (wid >> 2) * 64;
    const int m0   = blockIdx.y * 128;
    const int n0   = blockIdx.x * 128;

    const __nv_bfloat16* gsrc[4] = {
        Ahi + (size_t)m0 * 1024, Alo + (size_t)m0 * 1024,
        Bhi + (size_t)n0 * 1024, Blo + (size_t)n0 * 1024 };

    float acc[2][8][4];
#pragma unroll
    for (int i = 0; i < 2; i++)
#pragma unroll
        for (int j = 0; j < 8; j++)
#pragma unroll
            for (int r = 0; r < 4; r++) acc[i][j][r] = 0.f;

    auto issue = [&](int c, int s) {
#pragma unroll
        for (int l = 0; l < 8; l++) {
            int T  = l >> 1;
            int q  = tid + (l & 1) * 256;
            int row = q >> 2, cc = q & 3;
            uint32_t dst = sbase + s * STAGEB + T * TILEB + row * ROWB + cc * 16;
            const __nv_bfloat16* src = gsrc[T] + (size_t)row * 1024 + c * 32 + cc * 8;
            CP16(dst, src);
        }
        CP_COMMIT();
    };

    issue(0, 0);

    const int a_roff = (lane & 7) + ((lane >> 3) & 1) * 8;
    const int a_coff = ((lane >> 4) & 1) * 16;
    const int b_roff = (lane & 7) + ((lane >> 4) & 1) * 8;
    const int b_coff = ((lane >> 3) & 1) * 16;

    for (int c = 0; c < 32; c++) {
        const int s = c & 1;
        CP_WAIT0();
        __syncthreads();
        if (c < 31) issue(c + 1, s ^ 1);

        const uint32_t tA_hi = sbase + s * STAGEB;
        const uint32_t tA_lo = tA_hi + TILEB;
        const uint32_t tB_hi = tA_hi + 2 * TILEB;
        const uint32_t tB_lo = tA_hi + 3 * TILEB;

#pragma unroll
        for (int ks = 0; ks < 2; ks++) {
            uint32_t ah[2][4], al[2][4];
#pragma unroll
            for (int mt = 0; mt < 2; mt++) {
                uint32_t off = (uint32_t)(wm + mt * 16 + a_roff) * ROWB + ks * 32 + a_coff;
                ldsm4(ah[mt], tA_hi + off);
                ldsm4(al[mt], tA_lo + off);
            }
#pragma unroll
            for (int np = 0; np < 4; np++) {
                uint32_t bh[4], bl[4];
                uint32_t off = (uint32_t)(wn + np * 16 + b_roff) * ROWB + ks * 32 + b_coff;
                ldsm4(bh, tB_hi + off);
                ldsm4(bl, tB_lo + off);
#pragma unroll
                for (int mt = 0; mt < 2; mt++) {
#pragma unroll
                    for (int j = 0; j < 2; j++) {
                        float* d = acc[mt][np * 2 + j];
                        mma_bf16(d, ah[mt], bh + j * 2);
                        mma_bf16(d, ah[mt], bl + j * 2);
                        mma_bf16(d, al[mt], bh + j * 2);
                    }
                }
            }
        }
        __syncthreads();
    }

#pragma unroll
    for (int mt = 0; mt < 2; mt++) {
#pragma unroll
        for (int nt = 0; nt < 8; nt++) {
            int row0 = m0 + wm + mt * 16 + (lane >> 2);
            int col  = n0 + wn + nt * 8 + (lane & 3) * 2;
            float2 v0 = make_float2(acc[mt][nt][0], acc[mt][nt][1]);
            float2 v1 = make_float2(acc[mt][nt][2], acc[mt][nt][3]);
            if (mode == 1) {
                int h = col >> 6, dk = col & 63;
#pragma unroll
                for (int rr = 0; rr < 2; rr++) {
                    int row = row0 + rr * 8;
                    float2 v = rr ? v1 : v0;
                    size_t idx = (((size_t)((row >> 11) * H_ + h) * S_) + (row & 2047)) * DK_ + dk;
                    uint32_t hi, lo;
                    split2(v.x * scale, v.y * scale, hi, lo);
                    *reinterpret_cast<uint32_t*>(Chi + idx) = hi;
                    *reinterpret_cast<uint32_t*>(Clo + idx) = lo;
                }
            } else {
                *reinterpret_cast<float2*>(&Cf[(size_t)row0 * 1024 + col]) = v0;
                *reinterpret_cast<float2*>(&Cf[(size_t)(row0 + 8) * 1024 + col]) = v1;
            }
        }
    }
}

// ===========================================================================
// Flash attention on HMMA, 3-term bf16 split.
// CTA: 128 q-rows x full key loop (64-key blocks). 8 warps, 16 q-rows each.
// Q/K: [row][dk] bf16 hi/lo (Q pre-scaled by 1/8). V natural [key][dk] via
// ldmatrix.trans. Output written as bf16 hi/lo split into Ahi/Alo [m][1024].
// ===========================================================================
#define AROW 144
#define QOFF 0              // 2 * 128*144 = 36864
#define KOFF 36864          // 2 bufs * 2 (hi/lo) * 64*144 = 36864
#define VOFF 73728
#define MOFF 110592         // 2 * 256
#define ASMEM 111104

__global__ __launch_bounds__(256, 2) void attn_mma_kernel(
    const __nv_bfloat16* __restrict__ Qhi, const __nv_bfloat16* __restrict__ Qlo,
    const __nv_bfloat16* __restrict__ Khi, const __nv_bfloat16* __restrict__ Klo,
    const __nv_bfloat16* __restrict__ Vhi, const __nv_bfloat16* __restrict__ Vlo,
    const int* __restrict__ mask,
    __nv_bfloat16* __restrict__ Ohi, __nv_bfloat16* __restrict__ Olo)
{
    extern __shared__ char sma[];
    const uint32_t sbase = smem_u32(sma);
    const int tid  = threadIdx.x;
    const int lane = tid & 31;
    const int wid  = tid >> 5;
    const int wq   = wid * 16;          // warp's q-row offset in CTA tile
    const int q0   = blockIdx.x * 128;
    const int h    = blockIdx.y;
    const int b    = blockIdx.z;

    const size_t bh = ((size_t)b * H_ + h) * S_ * DK_;
    const __nv_bfloat16* Qhi_b = Qhi + bh;
    const __nv_bfloat16* Qlo_b = Qlo + bh;
    const __nv_bfloat16* Khi_b = Khi + bh;
    const __nv_bfloat16* Klo_b = Klo + bh;
    const __nv_bfloat16* Vhi_b = Vhi + bh;
    const __nv_bfloat16* Vlo_b = Vlo + bh;
    const int* mrow = mask + b * S_;

    // ---- prologue: Q tile (once) + K/V/mask block 0 ----
#pragma unroll
    for (int i = 0; i < 8; i++) {
        int c = tid + i * 256;             // 0..2047
        int T = c >> 10;
        int idx = c & 1023;
        int row = idx >> 3, ch = idx & 7;
        uint32_t dst = sbase + QOFF + T * 18432 + row * AROW + ch * 16;
        const __nv_bfloat16* src = (T ? Qlo_b : Qhi_b) + (size_t)(q0 + row) * 64 + ch * 8;
        CP16(dst, src);
    }
    auto issueKV = [&](int kb, int s) {
#pragma unroll
        for (int i = 0; i < 4; i++) {
            int c = tid + i * 256;         // 0..1023
            int T = c >> 9;
            int idx = c & 511;
            int row = idx >> 3, ch = idx & 7;
            uint32_t doff = s * 9216 + T * 18432 + (uint32_t)row * AROW + ch * 16;
            size_t soff = (size_t)(kb * 64 + row) * 64 + ch * 8;
            CP16(sbase + KOFF + doff, (T ? Klo_b : Khi_b) + soff);
            CP16(sbase + VOFF + doff, (T ? Vlo_b : Vhi_b) + soff);
        }
        if (tid < 16)
            CP16(sbase + MOFF + s * 256 + tid * 16, mrow + kb * 64 + tid * 4);
    };
    issueKV(0, 0);
    CP_COMMIT();

    // fragment addressing
    const int a_roff  = (lane & 7) + ((lane >> 3) & 1) * 8;
    const int a_coff  = ((lane >> 4) & 1) * 16;
    const int b_roff  = (lane & 7) + ((lane >> 4) & 1) * 8;
    const int b_coff  = ((lane >> 3) & 1) * 16;
    const int vb_roff = (lane & 7) + ((lane >> 3) & 1) * 8;   // key within chunk
    const int vb_coff = ((lane >> 4) & 1) * 16;               // dk bytes

    float O[8][4];
#pragma unroll
    for (int i = 0; i < 8; i++)
#pragma unroll
        for (int j = 0; j < 4; j++) O[i][j] = 0.f;
    float mM[2] = {-1e30f, -1e30f};
    float lL[2] = {0.f, 0.f};

    for (int kb = 0; kb < 32; kb++) {
        const int s = kb & 1;
        if (kb < 31) { issueKV(kb + 1, s ^ 1); CP_COMMIT(); CP_WAIT1(); }
        else         { CP_WAIT0(); }
        __syncthreads();

        // ---- scores = Q @ K^T (pre-scaled) ----
        float sc[8][4];
#pragma unroll
        for (int i = 0; i < 8; i++)
#pragma unroll
            for (int j = 0; j < 4; j++) sc[i][j] = 0.f;

        const uint32_t kb_hi = sbase + KOFF + s * 9216;
        const uint32_t kb_lo = kb_hi + 18432;
#pragma unroll
        for (int ks = 0; ks < 4; ks++) {
            uint32_t ah[4], al[4];
            uint32_t aoff = (uint32_t)(wq + a_roff) * AROW + ks * 32 + a_coff;
            ldsm4(ah, sbase + QOFF + aoff);
            ldsm4(al, sbase + QOFF + 18432 + aoff);
#pragma unroll
            for (int np = 0; np < 4; np++) {
                uint32_t bh2[4], bl2[4];
                uint32_t boff = (uint32_t)(np * 16 + b_roff) * AROW + ks * 32 + b_coff;
                ldsm4(bh2, kb_hi + boff);
                ldsm4(bl2, kb_lo + boff);
#pragma unroll
                for (int j = 0; j < 2; j++) {
                    float* d = sc[np * 2 + j];
                    mma_bf16(d, ah, bh2 + j * 2);
                    mma_bf16(d, ah, bl2 + j * 2);
                    mma_bf16(d, al, bh2 + j * 2);
                }
            }
        }

        // ---- mask ----
        const int c0 = (lane & 3) * 2;
#pragma unroll
        for (int st = 0; st < 8; st++) {
            int2 mv = *reinterpret_cast<const int2*>(
                sma + (MOFF + s * 256) + (st * 8 + c0) * 4);
            if (mv.x == 0) { sc[st][0] = -1e9f; sc[st][2] = -1e9f; }
            if (mv.y == 0) { sc[st][1] = -1e9f; sc[st][3] = -1e9f; }
        }

        // ---- online softmax (2 rows per thread: r, r+8) ----
        float alpha[2];
#pragma unroll
        for (int rh = 0; rh < 2; rh++) {
            float mx = -1e30f;
#pragma unroll
            for (int st = 0; st < 8; st++)
                mx = fmaxf(mx, fmaxf(sc[st][rh * 2], sc[st][rh * 2 + 1]));
            mx = fmaxf(mx, __shfl_xor_sync(0xffffffffu, mx, 1));
            mx = fmaxf(mx, __shfl_xor_sync(0xffffffffu, mx, 2));
            float mn = fmaxf(mM[rh], mx);
            alpha[rh] = __expf(mM[rh] - mn);
            mM[rh] = mn;
            float rsum = 0.f;
#pragma unroll
            for (int st = 0; st < 8; st++) {
                float p0 = __expf(sc[st][rh * 2] - mn);
                float p1 = __expf(sc[st][rh * 2 + 1] - mn);
                sc[st][rh * 2] = p0; sc[st][rh * 2 + 1] = p1;
                rsum += p0 + p1;
            }
            rsum += __shfl_xor_sync(0xffffffffu, rsum, 1);
            rsum += __shfl_xor_sync(0xffffffffu, rsum, 2);
            lL[rh] = lL[rh] * alpha[rh] + rsum;
        }
#pragma unroll
        for (int nt = 0; nt < 8; nt++) {
            O[nt][0] *= alpha[0]; O[nt][1] *= alpha[0];
            O[nt][2] *= alpha[1]; O[nt][3] *= alpha[1];
        }

        // ---- O += P @ V (P from registers, V via ldmatrix.trans) ----
        const uint32_t vb_hi = sbase + VOFF + s * 9216;
        const uint32_t vb_lo = vb_hi + 18432;
#pragma unroll
        for (int ks = 0; ks < 4; ks++) {   // 16-key chunks
            uint32_t ph[4], pl[4];
            split2(sc[2 * ks][0],     sc[2 * ks][1],     ph[0], pl[0]);
            split2(sc[2 * ks][2],     sc[2 * ks][3],     ph[1], pl[1]);
            split2(sc[2 * ks + 1][0], sc[2 * ks + 1][1], ph[2], pl[2]);
            split2(sc[2 * ks + 1][2], sc[2 * ks + 1][3], ph[3], pl[3]);
#pragma unroll
            for (int np = 0; np < 4; np++) {  // 16-dk chunks
                uint32_t vh[4], vl[4];
                uint32_t voff = (uint32_t)(ks * 16 + vb_roff) * AROW + np * 32 + vb_coff;
                ldsm4t(vh, vb_hi + voff);
                ldsm4t(vl, vb_lo + voff);
#pragma unroll
                for (int j = 0; j < 2; j++) {
                    float* d = O[np * 2 + j];
                    mma_bf16(d, ph, vh + j * 2);
                    mma_bf16(d, ph, vl + j * 2);
                    mma_bf16(d, pl, vh + j * 2);
                }
            }
        }
        __syncthreads();
    }

    // ---- epilogue: O /= l, write bf16 hi/lo into [m][1024] ----
#pragma unroll
    for (int rh = 0; rh < 2; rh++) {
        float inv = 1.f / lL[rh];
        int row = q0 + wq + (lane >> 2) + rh * 8;
        size_t mrow_o = ((size_t)b * S_ + row) * DM_ + h * 64;
#pragma unroll
        for (int nt = 0; nt < 8; nt++) {
            int col = nt * 8 + (lane & 3) * 2;
            uint32_t hi, lo;
            split2(O[nt][rh * 2] * inv, O[nt][rh * 2 + 1] * inv, hi, lo);
            *reinterpret_cast<uint32_t*>(Ohi + mrow_o + col) = hi;
            *reinterpret_cast<uint32_t*>(Olo + mrow_o + col) = lo;
        }
    }
}

// ---------------------------------------------------------------------------
extern "C" void kernel_launch(void* const* d_in, const int* in_sizes, int n_in,
                              void* d_out, int out_size)
{
    const float* q    = (const float*)d_in[0];
    const float* k    = (const float*)d_in[1];
    const float* v    = (const float*)d_in[2];
    const int*   mask = (const int*)d_in[3];
    const float* Wq   = (const float*)d_in[4];
    const float* Wk   = (const float*)d_in[5];
    const float* Wv   = (const float*)d_in[6];
    const float* Wo   = (const float*)d_in[7];
    float* out = (float*)d_out;

    __nv_bfloat16 *ahi, *alo, *whi, *wlo, *qhi, *qlo, *khi, *klo, *vhi, *vlo;
    cudaGetSymbolAddress((void**)&ahi, g_Ahi);
    cudaGetSymbolAddress((void**)&alo, g_Alo);
    cudaGetSymbolAddress((void**)&whi, g_Whi);
    cudaGetSymbolAddress((void**)&wlo, g_Wlo);
    cudaGetSymbolAddress((void**)&qhi, g_Qhi);
    cudaGetSymbolAddress((void**)&qlo, g_Qlo);
    cudaGetSymbolAddress((void**)&khi, g_Khi);
    cudaGetSymbolAddress((void**)&klo, g_Klo);
    cudaGetSymbolAddress((void**)&vhi, g_Vhi);
    cudaGetSymbolAddress((void**)&vlo, g_Vlo);

    cudaFuncSetAttribute(gemm_bf16_kernel,
                         cudaFuncAttributeMaxDynamicSharedMemorySize, SMEMG);
    cudaFuncSetAttribute(attn_mma_kernel,
                         cudaFuncAttributeMaxDynamicSharedMemorySize, ASMEM);

    const int nA4 = M_ * DM_ / 4;
    const int nW4 = DM_ * DM_ / 4;
    dim3 gg(DM_ / 128, M_ / 128);

    // Q projection (pre-scale by 1/sqrt(dk) = 0.125)
    split_kernel<<<nA4 / 256, 256>>>(q, ahi, alo);
    split_kernel<<<nW4 / 256, 256>>>(Wq, whi, wlo);
    gemm_bf16_kernel<<<gg, 256, SMEMG>>>(ahi, alo, whi, wlo, nullptr, qhi, qlo, 1, 0.125f);
    // K projection
    split_kernel<<<nA4 / 256, 256>>>(k, ahi, alo);
    split_kernel<<<nW4 / 256, 256>>>(Wk, whi, wlo);
    gemm_bf16_kernel<<<gg, 256, SMEMG>>>(ahi, alo, whi, wlo, nullptr, khi, klo, 1, 1.0f);
    // V projection
    split_kernel<<<nA4 / 256, 256>>>(v, ahi, alo);
    split_kernel<<<nW4 / 256, 256>>>(Wv, whi, wlo);
    gemm_bf16_kernel<<<gg, 256, SMEMG>>>(ahi, alo, whi, wlo, nullptr, vhi, vlo, 1, 1.0f);

    // attention (writes bf16 hi/lo merged-head output into ahi/alo)
    attn_mma_kernel<<<dim3(S_ / 128, H_, B_), 256, ASMEM>>>(
        qhi, qlo, khi, klo, vhi, vlo, mask, ahi, alo);

    // output projection (fp32 result)
    split_kernel<<<nW4 / 256, 256>>>(Wo, whi, wlo);
    gemm_bf16_kernel<<<gg, 256, SMEMG>>>(ahi, alo, whi, wlo, out, nullptr, nullptr, 0, 1.0f);
}